// round 1
// baseline (speedup 1.0000x reference)
#include <cuda_runtime.h>

// Batched outer product: out[i, j*K + l] = x[i,j] * y[i,l]
// n=4096, m=256, k=256  → out row = 65536 f32 = 16384 float4
// Pure store-bandwidth kernel: 1.07 GB written, ~8 MB read.

static constexpr int M = 256;   // x row length
static constexpr int K = 256;   // y row length
static constexpr int ROW_F4 = (M * K) / 4;  // 16384 float4 per output row

__global__ __launch_bounds__(256, 8)
void omul_kernel(const float* __restrict__ x,
                 const float* __restrict__ y,
                 float4* __restrict__ out)
{
    __shared__ float xs[M];

    const int row = blockIdx.x;
    const int t   = threadIdx.x;

    // Stage x row in smem (broadcast reads later), y float4 in a register.
    xs[t] = x[(size_t)row * M + t];
    // Each thread's l-chunk is fixed: idx & 63 == t & 63 for all iterations.
    const float4 yv = reinterpret_cast<const float4*>(y + (size_t)row * K)[t & 63];
    __syncthreads();

    float4* o = out + (size_t)row * ROW_F4;

    // 64 iterations × 256 threads = 16384 float4 stores, fully coalesced.
    // idx = i*256 + t; j = idx>>6 (x index), l4 = idx&63 (y float4 index).
    #pragma unroll 8
    for (int i = 0; i < 64; i++) {
        const int idx = i * 256 + t;
        const float xv = xs[idx >> 6];        // broadcast within 64-thread groups
        float4 r;
        r.x = xv * yv.x;
        r.y = xv * yv.y;
        r.z = xv * yv.z;
        r.w = xv * yv.w;
        __stcs(&o[idx], r);                   // streaming store: no L2 reuse
    }
}

extern "C" void kernel_launch(void* const* d_in, const int* in_sizes, int n_in,
                              void* d_out, int out_size)
{
    const float* x = (const float*)d_in[0];
    const float* y = (const float*)d_in[1];
    float4* out = (float4*)d_out;

    const int n = in_sizes[0] / M;  // 4096 rows
    omul_kernel<<<n, 256>>>(x, y, out);
}